// round 16
// baseline (speedup 1.0000x reference)
#include <cuda_runtime.h>
#include <cuda_bf16.h>

// NeuMIP v1, round 16: R15 (2 pts/thread, all-const weights, activations in
// per-thread SMEM columns) with ONE change: __launch_bounds__(128, 5) caps
// registers at 102 -> 5 CTAs = 20 warps/SM (was 128 regs / 16 warps).
// Ports (LDC ~127us, FMA ~138us, L1 ~55us) unchanged; the +25% warps target
// the ~100us of unhidden latency ncu showed (no pipe saturated, issue 42%).

#define RESOL 512
#define RMASK 511
#define HID 32
#define NSLOPE 0.01f
#define THREADS 128
#define PTS_PER_BLOCK 256

typedef unsigned long long ull;

// Constant image: transposed weights [K][32] packed neuron pairs; biases;
// head weights duplicated per-lane for packed f32x2 dot products.
struct __align__(16) CW {
    ulonglong2 ow0T[10 * 8];
    ulonglong2 ow1T[32 * 8];
    ulonglong2 ow2T[32 * 8];
    ulonglong2 rw0T[12 * 8];
    ulonglong2 rw1T[32 * 8];
    ulonglong2 rw2T[32 * 8];
    ull ob0[16]; ull ob1[16]; ull ob2[16];
    ull rb0[16]; ull rb1[16]; ull rb2[16];
    ull ow3d[32];        // (w_i, w_i) duplicated pairs
    ull rw3d[3][32];
    float ob3; float rb3[3];
};

__constant__ CW cw;
__device__ CW g_stage;

__device__ __forceinline__ float leaky(float x) {
    return fmaxf(x, NSLOPE * x);  // slope < 1
}

__device__ __forceinline__ ull fma2(ull a, ull b, ull c) {
    ull d;
    asm("fma.rn.f32x2 %0, %1, %2, %3;" : "=l"(d) : "l"(a), "l"(b), "l"(c));
    return d;
}

__device__ __forceinline__ ull pack2(float lo, float hi) {
    ull d;
    asm("mov.b64 %0, {%1, %2};" : "=l"(d) : "f"(lo), "f"(hi));
    return d;
}

__device__ __forceinline__ void unpack2(ull v, float& lo, float& hi) {
    asm("mov.b64 {%0, %1}, %2;" : "=f"(lo), "=f"(hi) : "l"(v));
}

// ---------------- prep kernel ----------------

__device__ __forceinline__ void d_tpose(float* dstf, const float* src,
                                        int K, int tid, int nt) {
    // src [32][K] -> dst [K][32]
    for (int idx = tid; idx < K * 32; idx += nt) {
        int i = idx / 32, j = idx - i * 32;
        dstf[idx] = src[j * K + i];
    }
}

__device__ __forceinline__ void d_copy(float* dst, const float* src, int n,
                                       int tid, int nt) {
    for (int i = tid; i < n; i += nt) dst[i] = src[i];
}

__device__ __forceinline__ ull dup2(float w) {
    unsigned u = __float_as_uint(w);
    return ((ull)u << 32) | u;
}

__global__ void prep_kernel(const float* ow0, const float* ob0,
                            const float* ow1, const float* ob1,
                            const float* ow2, const float* ob2,
                            const float* ow3, const float* ob3,
                            const float* rw0, const float* rb0,
                            const float* rw1, const float* rb1,
                            const float* rw2, const float* rb2,
                            const float* rw3, const float* rb3) {
    const int tid = threadIdx.x, nt = blockDim.x;
    d_tpose((float*)g_stage.ow0T, ow0, 10, tid, nt);
    d_tpose((float*)g_stage.ow1T, ow1, 32, tid, nt);
    d_tpose((float*)g_stage.ow2T, ow2, 32, tid, nt);
    d_tpose((float*)g_stage.rw0T, rw0, 12, tid, nt);
    d_tpose((float*)g_stage.rw1T, rw1, 32, tid, nt);
    d_tpose((float*)g_stage.rw2T, rw2, 32, tid, nt);
    d_copy((float*)g_stage.ob0, ob0, 32, tid, nt);
    d_copy((float*)g_stage.ob1, ob1, 32, tid, nt);
    d_copy((float*)g_stage.ob2, ob2, 32, tid, nt);
    d_copy((float*)g_stage.rb0, rb0, 32, tid, nt);
    d_copy((float*)g_stage.rb1, rb1, 32, tid, nt);
    d_copy((float*)g_stage.rb2, rb2, 32, tid, nt);
    for (int i = tid; i < 32; i += nt) {
        g_stage.ow3d[i] = dup2(ow3[i]);
        g_stage.rw3d[0][i] = dup2(rw3[0 * 32 + i]);
        g_stage.rw3d[1][i] = dup2(rw3[1 * 32 + i]);
        g_stage.rw3d[2][i] = dup2(rw3[2 * 32 + i]);
    }
    if (tid == 0) {
        g_stage.ob3 = ob3[0];
        g_stage.rb3[0] = rb3[0];
        g_stage.rb3[1] = rb3[1];
        g_stage.rb3[2] = rb3[2];
    }
}

// ---------------- main kernel ----------------

// 8-channel bilinear with wrap.
__device__ __forceinline__ void bilin8(const float4* __restrict__ t,
                                       float u, float v, float* __restrict__ o) {
    float px = u * (float)RESOL - 0.5f;
    float py = v * (float)RESOL - 0.5f;
    float fpx = floorf(px), fpy = floorf(py);
    float fx = px - fpx, fy = py - fpy;
    int ix = (int)fpx, iy = (int)fpy;
    int x0 = ix & RMASK, x1 = (ix + 1) & RMASK;
    int y0 = iy & RMASK, y1 = (iy + 1) & RMASK;
    float w00 = (1.0f - fx) * (1.0f - fy);
    float w01 = fx * (1.0f - fy);
    float w10 = (1.0f - fx) * fy;
    float w11 = fx * fy;
    const float4* p00 = t + (size_t)(y0 * RESOL + x0) * 2;
    const float4* p01 = t + (size_t)(y0 * RESOL + x1) * 2;
    const float4* p10 = t + (size_t)(y1 * RESOL + x0) * 2;
    const float4* p11 = t + (size_t)(y1 * RESOL + x1) * 2;
    float4 a00 = __ldg(p00),     b00 = __ldg(p00 + 1);
    float4 a01 = __ldg(p01),     b01 = __ldg(p01 + 1);
    float4 a10 = __ldg(p10),     b10 = __ldg(p10 + 1);
    float4 a11 = __ldg(p11),     b11 = __ldg(p11 + 1);
    o[0] = w00 * a00.x + w01 * a01.x + w10 * a10.x + w11 * a11.x;
    o[1] = w00 * a00.y + w01 * a01.y + w10 * a10.y + w11 * a11.y;
    o[2] = w00 * a00.z + w01 * a01.z + w10 * a10.z + w11 * a11.z;
    o[3] = w00 * a00.w + w01 * a01.w + w10 * a10.w + w11 * a11.w;
    o[4] = w00 * b00.x + w01 * b01.x + w10 * b10.x + w11 * b11.x;
    o[5] = w00 * b00.y + w01 * b01.y + w10 * b10.y + w11 * b11.y;
    o[6] = w00 * b00.z + w01 * b01.z + w10 * b10.z + w11 * b11.z;
    o[7] = w00 * b00.w + w01 * b01.w + w10 * b10.w + w11 * b11.w;
}

// One layer, 2 points per thread. Inputs read from this thread's smem column
// (float2 = (pt0,pt1) per channel), outputs written back in place.
// Weights: 8 LDC.128 per input row (serves both points).
template <int K>
__device__ __forceinline__ void layerC2S(const ulonglong2* __restrict__ wT,
                                         const ull* __restrict__ bias,
                                         float2* __restrict__ col) {
    ull acc0[16], acc1[16];
#pragma unroll
    for (int k = 0; k < 16; k++) { ull b = bias[k]; acc0[k] = b; acc1[k] = b; }
#pragma unroll
    for (int i = 0; i < K; i++) {
        float2 v = col[i * THREADS];
        ull a0 = pack2(v.x, v.x);
        ull a1 = pack2(v.y, v.y);
#pragma unroll
        for (int q = 0; q < 8; q++) {
            ulonglong2 w = wT[i * 8 + q];
            acc0[2 * q]     = fma2(a0, w.x, acc0[2 * q]);
            acc0[2 * q + 1] = fma2(a0, w.y, acc0[2 * q + 1]);
            acc1[2 * q]     = fma2(a1, w.x, acc1[2 * q]);
            acc1[2 * q + 1] = fma2(a1, w.y, acc1[2 * q + 1]);
        }
    }
#pragma unroll
    for (int k = 0; k < 16; k++) {
        float x0, y0, x1, y1;
        unpack2(acc0[k], x0, y0);   // pt0: neurons 2k, 2k+1
        unpack2(acc1[k], x1, y1);   // pt1: neurons 2k, 2k+1
        col[(2 * k) * THREADS]     = make_float2(leaky(x0), leaky(x1));
        col[(2 * k + 1) * THREADS] = make_float2(leaky(y0), leaky(y1));
    }
}

// Packed head: returns (dot_pt0, dot_pt1) via f32x2 over the smem column.
__device__ __forceinline__ ull head2(const ull* __restrict__ wd,
                                     const float2* __restrict__ col) {
    const ull* colu = reinterpret_cast<const ull*>(col);
    ull acc = pack2(0.0f, 0.0f);
#pragma unroll
    for (int i = 0; i < 32; i++)
        acc = fma2(colu[i * THREADS], wd[i], acc);
    return acc;
}

__global__ void __launch_bounds__(THREADS, 5)
neumip_kernel(const float* __restrict__ cam,
              const float* __restrict__ light,
              const float* __restrict__ uv,
              const float* __restrict__ offset_tex,
              const float* __restrict__ rgb_tex,
              float* __restrict__ out, int n) {
    __shared__ float2 act[HID][THREADS];   // 32 KB: channel-major, lane-contig
    const int tid = threadIdx.x;
    float2* col = &act[0][tid];

    const int p0 = blockIdx.x * PTS_PER_BLOCK + tid;
    const int p1 = p0 + THREADS;
    if (p0 >= n) return;
    const int p1c = p1 < n ? p1 : p0;   // clamp (n is a multiple of 256 anyway)

    const float2* cam2 = reinterpret_cast<const float2*>(cam);
    const float2* uv2p = reinterpret_cast<const float2*>(uv);
    const float2* li2 = reinterpret_cast<const float2*>(light);

    const float2 c0 = __ldg(cam2 + p0);
    const float2 c1 = __ldg(cam2 + p1c);
    const float2 t0 = __ldg(uv2p + p0);
    const float2 t1 = __ldg(uv2p + p1c);

    // ---- offset gathers -> smem channels 0..9 ----
    {
        float la[8], lb[8];
        bilin8(reinterpret_cast<const float4*>(offset_tex), t0.x, t0.y, la);
        bilin8(reinterpret_cast<const float4*>(offset_tex), t1.x, t1.y, lb);
#pragma unroll
        for (int c = 0; c < 8; c++) col[c * THREADS] = make_float2(la[c], lb[c]);
        col[8 * THREADS] = make_float2(c0.x, c1.x);
        col[9 * THREADS] = make_float2(c0.y, c1.y);
    }

    // ---- depth MLP ----
    layerC2S<10>(cw.ow0T, cw.ob0, col);
    layerC2S<HID>(cw.ow1T, cw.ob1, col);
    layerC2S<HID>(cw.ow2T, cw.ob2, col);

    float dep0, dep1;
    {
        ull d = head2(cw.ow3d, col);
        unpack2(d, dep0, dep1);
        dep0 += cw.ob3;
        dep1 += cw.ob3;
    }

    // ---- parallax + rgb gathers -> smem channels 0..11 ----
    {
        float z0 = sqrtf(fmaxf(1.0f - (c0.x * c0.x + c0.y * c0.y), 1e-6f));
        float z1 = sqrtf(fmaxf(1.0f - (c1.x * c1.x + c1.y * c1.y), 1e-6f));
        float s0 = dep0 / z0, s1 = dep1 / z1;
        float u10 = t0.x + c0.x * s0, v10 = t0.y + c0.y * s0;
        float u11 = t1.x + c1.x * s1, v11 = t1.y + c1.y * s1;
        const float2 l0 = __ldg(li2 + p0);
        const float2 l1 = __ldg(li2 + p1c);
        float la[8], lb[8];
        bilin8(reinterpret_cast<const float4*>(rgb_tex), u10, v10, la);
        bilin8(reinterpret_cast<const float4*>(rgb_tex), u11, v11, lb);
        col[0 * THREADS] = make_float2(l0.x, l1.x);
        col[1 * THREADS] = make_float2(l0.y, l1.y);
        col[2 * THREADS] = make_float2(c0.x, c1.x);
        col[3 * THREADS] = make_float2(c0.y, c1.y);
#pragma unroll
        for (int c = 0; c < 8; c++)
            col[(4 + c) * THREADS] = make_float2(la[c], lb[c]);
    }

    // ---- rgb MLP ----
    layerC2S<12>(cw.rw0T, cw.rb0, col);
    layerC2S<HID>(cw.rw1T, cw.rb1, col);
    layerC2S<HID>(cw.rw2T, cw.rb2, col);

    // ---- rgb head (packed over both points) ----
    float o00, o01, o02, o10, o11, o12;
    {
        float a, b;
        unpack2(head2(cw.rw3d[0], col), a, b);
        o00 = a + cw.rb3[0]; o10 = b + cw.rb3[0];
        unpack2(head2(cw.rw3d[1], col), a, b);
        o01 = a + cw.rb3[1]; o11 = b + cw.rb3[1];
        unpack2(head2(cw.rw3d[2], col), a, b);
        o02 = a + cw.rb3[2]; o12 = b + cw.rb3[2];
    }
    out[3 * p0 + 0] = o00;
    out[3 * p0 + 1] = o01;
    out[3 * p0 + 2] = o02;
    if (p1 < n) {
        out[3 * p1 + 0] = o10;
        out[3 * p1 + 1] = o11;
        out[3 * p1 + 2] = o12;
    }
}

extern "C" void kernel_launch(void* const* d_in, const int* in_sizes, int n_in,
                              void* d_out, int out_size) {
    const float* cam        = (const float*)d_in[0];
    const float* light      = (const float*)d_in[1];
    const float* uv         = (const float*)d_in[2];
    const float* offset_tex = (const float*)d_in[3];
    const float* rgb_tex    = (const float*)d_in[4];

    prep_kernel<<<1, 256>>>((const float*)d_in[5],  (const float*)d_in[6],
                            (const float*)d_in[7],  (const float*)d_in[8],
                            (const float*)d_in[9],  (const float*)d_in[10],
                            (const float*)d_in[11], (const float*)d_in[12],
                            (const float*)d_in[13], (const float*)d_in[14],
                            (const float*)d_in[15], (const float*)d_in[16],
                            (const float*)d_in[17], (const float*)d_in[18],
                            (const float*)d_in[19], (const float*)d_in[20]);

    void* stage_ptr = nullptr;
    cudaGetSymbolAddress(&stage_ptr, g_stage);
    cudaMemcpyToSymbolAsync(cw, stage_ptr, sizeof(CW), 0,
                            cudaMemcpyDeviceToDevice, 0);

    const int n = in_sizes[0] / 2;  // camera_dir is (B, 2)
    const int blocks = (n + PTS_PER_BLOCK - 1) / PTS_PER_BLOCK;
    neumip_kernel<<<blocks, THREADS>>>(cam, light, uv, offset_tex, rgb_tex,
                                       (float*)d_out, n);
}

// round 17
// speedup vs baseline: 1.0707x; 1.0707x over previous
#include <cuda_runtime.h>
#include <cuda_bf16.h>

// NeuMIP v1, round 17: R15 skeleton (2 pts/thread, smem activation columns,
// all-uniform weight loads) + BY-ROW port mixing: within every layer, the
// first rows stream from __constant__ (LDC.128, floor-8 issue) and the last
// ~25% of rows from smem (LDS.128, floor-2 issue). Both streams uniform,
// interleaved inside each layer -> ports overlap regardless of warp phase.
// Const port ~200K cyc/SM, L1 ~225K cyc/SM (weights+acts+textures): balanced.

#define RESOL 512
#define RMASK 511
#define HID 32
#define NSLOPE 0.01f
#define THREADS 128
#define PTS_PER_BLOCK 256

typedef unsigned long long ull;

// Constant image: transposed weights [K][32] packed neuron pairs; biases;
// head weights duplicated per-lane for packed f32x2 dot products.
struct __align__(16) CW {
    ulonglong2 ow0T[10 * 8];
    ulonglong2 ow1T[32 * 8];
    ulonglong2 ow2T[32 * 8];
    ulonglong2 rw0T[12 * 8];
    ulonglong2 rw1T[32 * 8];
    ulonglong2 rw2T[32 * 8];
    ull ob0[16]; ull ob1[16]; ull ob2[16];
    ull rb0[16]; ull rb1[16]; ull rb2[16];
    ull ow3d[32];        // (w_i, w_i) duplicated pairs
    ull rw3d[3][32];
    float ob3; float rb3[3];
};

__constant__ CW cw;
__device__ CW g_stage;

// Row split per layer: rows [0, KC) from const, rows [KC, K) from smem.
#define OW0_KC 8
#define OW1_KC 24
#define OW2_KC 24
#define RW0_KC 9
#define RW1_KC 24
#define RW2_KC 24

// smem weight tails, transposed [KS][32]
struct __align__(16) SWT {
    float ow0[2 * 32];
    float ow1[8 * 32];
    float ow2[8 * 32];
    float rw0[3 * 32];
    float rw1[8 * 32];
    float rw2[8 * 32];
};

__device__ __forceinline__ float leaky(float x) {
    return fmaxf(x, NSLOPE * x);  // slope < 1
}

__device__ __forceinline__ ull fma2(ull a, ull b, ull c) {
    ull d;
    asm("fma.rn.f32x2 %0, %1, %2, %3;" : "=l"(d) : "l"(a), "l"(b), "l"(c));
    return d;
}

__device__ __forceinline__ ull pack2(float lo, float hi) {
    ull d;
    asm("mov.b64 %0, {%1, %2};" : "=l"(d) : "f"(lo), "f"(hi));
    return d;
}

__device__ __forceinline__ void unpack2(ull v, float& lo, float& hi) {
    asm("mov.b64 {%0, %1}, %2;" : "=f"(lo), "=f"(hi) : "l"(v));
}

// ---------------- prep kernel ----------------

__device__ __forceinline__ void d_tpose(float* dstf, const float* src,
                                        int K, int tid, int nt) {
    // src [32][K] -> dst [K][32]
    for (int idx = tid; idx < K * 32; idx += nt) {
        int i = idx / 32, j = idx - i * 32;
        dstf[idx] = src[j * K + i];
    }
}

__device__ __forceinline__ void d_copy(float* dst, const float* src, int n,
                                       int tid, int nt) {
    for (int i = tid; i < n; i += nt) dst[i] = src[i];
}

__device__ __forceinline__ ull dup2(float w) {
    unsigned u = __float_as_uint(w);
    return ((ull)u << 32) | u;
}

__global__ void prep_kernel(const float* ow0, const float* ob0,
                            const float* ow1, const float* ob1,
                            const float* ow2, const float* ob2,
                            const float* ow3, const float* ob3,
                            const float* rw0, const float* rb0,
                            const float* rw1, const float* rb1,
                            const float* rw2, const float* rb2,
                            const float* rw3, const float* rb3) {
    const int tid = threadIdx.x, nt = blockDim.x;
    d_tpose((float*)g_stage.ow0T, ow0, 10, tid, nt);
    d_tpose((float*)g_stage.ow1T, ow1, 32, tid, nt);
    d_tpose((float*)g_stage.ow2T, ow2, 32, tid, nt);
    d_tpose((float*)g_stage.rw0T, rw0, 12, tid, nt);
    d_tpose((float*)g_stage.rw1T, rw1, 32, tid, nt);
    d_tpose((float*)g_stage.rw2T, rw2, 32, tid, nt);
    d_copy((float*)g_stage.ob0, ob0, 32, tid, nt);
    d_copy((float*)g_stage.ob1, ob1, 32, tid, nt);
    d_copy((float*)g_stage.ob2, ob2, 32, tid, nt);
    d_copy((float*)g_stage.rb0, rb0, 32, tid, nt);
    d_copy((float*)g_stage.rb1, rb1, 32, tid, nt);
    d_copy((float*)g_stage.rb2, rb2, 32, tid, nt);
    for (int i = tid; i < 32; i += nt) {
        g_stage.ow3d[i] = dup2(ow3[i]);
        g_stage.rw3d[0][i] = dup2(rw3[0 * 32 + i]);
        g_stage.rw3d[1][i] = dup2(rw3[1 * 32 + i]);
        g_stage.rw3d[2][i] = dup2(rw3[2 * 32 + i]);
    }
    if (tid == 0) {
        g_stage.ob3 = ob3[0];
        g_stage.rb3[0] = rb3[0];
        g_stage.rb3[1] = rb3[1];
        g_stage.rb3[2] = rb3[2];
    }
}

// ---------------- main kernel ----------------

// transpose weight-tail rows [KC, K) of src [32][K] into dst [KS][32]
__device__ __forceinline__ void tcopy_tail(float* dst, const float* src,
                                           int K, int KC, int KS,
                                           int tid, int nt) {
    for (int idx = tid; idx < KS * 32; idx += nt) {
        int r = idx >> 5, j = idx & 31;
        dst[idx] = src[j * K + (KC + r)];
    }
}

// 8-channel bilinear with wrap.
__device__ __forceinline__ void bilin8(const float4* __restrict__ t,
                                       float u, float v, float* __restrict__ o) {
    float px = u * (float)RESOL - 0.5f;
    float py = v * (float)RESOL - 0.5f;
    float fpx = floorf(px), fpy = floorf(py);
    float fx = px - fpx, fy = py - fpy;
    int ix = (int)fpx, iy = (int)fpy;
    int x0 = ix & RMASK, x1 = (ix + 1) & RMASK;
    int y0 = iy & RMASK, y1 = (iy + 1) & RMASK;
    float w00 = (1.0f - fx) * (1.0f - fy);
    float w01 = fx * (1.0f - fy);
    float w10 = (1.0f - fx) * fy;
    float w11 = fx * fy;
    const float4* p00 = t + (size_t)(y0 * RESOL + x0) * 2;
    const float4* p01 = t + (size_t)(y0 * RESOL + x1) * 2;
    const float4* p10 = t + (size_t)(y1 * RESOL + x0) * 2;
    const float4* p11 = t + (size_t)(y1 * RESOL + x1) * 2;
    float4 a00 = __ldg(p00),     b00 = __ldg(p00 + 1);
    float4 a01 = __ldg(p01),     b01 = __ldg(p01 + 1);
    float4 a10 = __ldg(p10),     b10 = __ldg(p10 + 1);
    float4 a11 = __ldg(p11),     b11 = __ldg(p11 + 1);
    o[0] = w00 * a00.x + w01 * a01.x + w10 * a10.x + w11 * a11.x;
    o[1] = w00 * a00.y + w01 * a01.y + w10 * a10.y + w11 * a11.y;
    o[2] = w00 * a00.z + w01 * a01.z + w10 * a10.z + w11 * a11.z;
    o[3] = w00 * a00.w + w01 * a01.w + w10 * a10.w + w11 * a11.w;
    o[4] = w00 * b00.x + w01 * b01.x + w10 * b10.x + w11 * b11.x;
    o[5] = w00 * b00.y + w01 * b01.y + w10 * b10.y + w11 * b11.y;
    o[6] = w00 * b00.z + w01 * b01.z + w10 * b10.z + w11 * b11.z;
    o[7] = w00 * b00.w + w01 * b01.w + w10 * b10.w + w11 * b11.w;
}

// One layer, 2 points/thread, mixed ports by row:
//  rows [0, KC) weights from __constant__ (8x LDC.128),
//  rows [KC, KC+KS) weights from smem (8x uniform LDS.128).
template <int KC, int KS>
__device__ __forceinline__ void layerM(const ulonglong2* __restrict__ wT,
                                       const float* __restrict__ sw,
                                       const ull* __restrict__ bias,
                                       float2* __restrict__ col) {
    ull acc0[16], acc1[16];
#pragma unroll
    for (int k = 0; k < 16; k++) { ull b = bias[k]; acc0[k] = b; acc1[k] = b; }
#pragma unroll
    for (int i = 0; i < KC; i++) {
        float2 v = col[i * THREADS];
        ull a0 = pack2(v.x, v.x);
        ull a1 = pack2(v.y, v.y);
#pragma unroll
        for (int q = 0; q < 8; q++) {
            ulonglong2 w = wT[i * 8 + q];
            acc0[2 * q]     = fma2(a0, w.x, acc0[2 * q]);
            acc0[2 * q + 1] = fma2(a0, w.y, acc0[2 * q + 1]);
            acc1[2 * q]     = fma2(a1, w.x, acc1[2 * q]);
            acc1[2 * q + 1] = fma2(a1, w.y, acc1[2 * q + 1]);
        }
    }
#pragma unroll
    for (int i = 0; i < KS; i++) {
        float2 v = col[(KC + i) * THREADS];
        ull a0 = pack2(v.x, v.x);
        ull a1 = pack2(v.y, v.y);
        const ulonglong2* w2 = reinterpret_cast<const ulonglong2*>(sw + i * HID);
#pragma unroll
        for (int q = 0; q < 8; q++) {
            ulonglong2 w = w2[q];
            acc0[2 * q]     = fma2(a0, w.x, acc0[2 * q]);
            acc0[2 * q + 1] = fma2(a0, w.y, acc0[2 * q + 1]);
            acc1[2 * q]     = fma2(a1, w.x, acc1[2 * q]);
            acc1[2 * q + 1] = fma2(a1, w.y, acc1[2 * q + 1]);
        }
    }
#pragma unroll
    for (int k = 0; k < 16; k++) {
        float x0, y0, x1, y1;
        unpack2(acc0[k], x0, y0);
        unpack2(acc1[k], x1, y1);
        col[(2 * k) * THREADS]     = make_float2(leaky(x0), leaky(x1));
        col[(2 * k + 1) * THREADS] = make_float2(leaky(y0), leaky(y1));
    }
}

// Packed head: returns (dot_pt0, dot_pt1) via f32x2 over the smem column.
__device__ __forceinline__ ull head2(const ull* __restrict__ wd,
                                     const float2* __restrict__ col) {
    const ull* colu = reinterpret_cast<const ull*>(col);
    ull acc = pack2(0.0f, 0.0f);
#pragma unroll
    for (int i = 0; i < 32; i++)
        acc = fma2(colu[i * THREADS], wd[i], acc);
    return acc;
}

__global__ void __launch_bounds__(THREADS, 4)
neumip_kernel(const float* __restrict__ cam,
              const float* __restrict__ light,
              const float* __restrict__ uv,
              const float* __restrict__ offset_tex,
              const float* __restrict__ rgb_tex,
              const float* __restrict__ gow0, const float* __restrict__ gow1,
              const float* __restrict__ gow2, const float* __restrict__ grw0,
              const float* __restrict__ grw1, const float* __restrict__ grw2,
              float* __restrict__ out, int n) {
    __shared__ float2 act[HID][THREADS];   // 32 KB activation columns
    __shared__ SWT swt;                    // ~4.6 KB weight tails
    const int tid = threadIdx.x;
    float2* col = &act[0][tid];

    tcopy_tail(swt.ow0, gow0, 10, OW0_KC, 10 - OW0_KC, tid, THREADS);
    tcopy_tail(swt.ow1, gow1, 32, OW1_KC, 32 - OW1_KC, tid, THREADS);
    tcopy_tail(swt.ow2, gow2, 32, OW2_KC, 32 - OW2_KC, tid, THREADS);
    tcopy_tail(swt.rw0, grw0, 12, RW0_KC, 12 - RW0_KC, tid, THREADS);
    tcopy_tail(swt.rw1, grw1, 32, RW1_KC, 32 - RW1_KC, tid, THREADS);
    tcopy_tail(swt.rw2, grw2, 32, RW2_KC, 32 - RW2_KC, tid, THREADS);
    __syncthreads();

    const int p0 = blockIdx.x * PTS_PER_BLOCK + tid;
    const int p1 = p0 + THREADS;
    if (p0 >= n) return;
    const int p1c = p1 < n ? p1 : p0;

    const float2* cam2 = reinterpret_cast<const float2*>(cam);
    const float2* uv2p = reinterpret_cast<const float2*>(uv);
    const float2* li2 = reinterpret_cast<const float2*>(light);

    const float2 c0 = __ldg(cam2 + p0);
    const float2 c1 = __ldg(cam2 + p1c);
    const float2 t0 = __ldg(uv2p + p0);
    const float2 t1 = __ldg(uv2p + p1c);

    // ---- offset gathers -> smem channels 0..9 ----
    {
        float la[8], lb[8];
        bilin8(reinterpret_cast<const float4*>(offset_tex), t0.x, t0.y, la);
        bilin8(reinterpret_cast<const float4*>(offset_tex), t1.x, t1.y, lb);
#pragma unroll
        for (int c = 0; c < 8; c++) col[c * THREADS] = make_float2(la[c], lb[c]);
        col[8 * THREADS] = make_float2(c0.x, c1.x);
        col[9 * THREADS] = make_float2(c0.y, c1.y);
    }

    // ---- depth MLP ----
    layerM<OW0_KC, 10 - OW0_KC>(cw.ow0T, swt.ow0, cw.ob0, col);
    layerM<OW1_KC, 32 - OW1_KC>(cw.ow1T, swt.ow1, cw.ob1, col);
    layerM<OW2_KC, 32 - OW2_KC>(cw.ow2T, swt.ow2, cw.ob2, col);

    float dep0, dep1;
    {
        ull d = head2(cw.ow3d, col);
        unpack2(d, dep0, dep1);
        dep0 += cw.ob3;
        dep1 += cw.ob3;
    }

    // ---- parallax + rgb gathers -> smem channels 0..11 ----
    {
        float z0 = sqrtf(fmaxf(1.0f - (c0.x * c0.x + c0.y * c0.y), 1e-6f));
        float z1 = sqrtf(fmaxf(1.0f - (c1.x * c1.x + c1.y * c1.y), 1e-6f));
        float s0 = dep0 / z0, s1 = dep1 / z1;
        float u10 = t0.x + c0.x * s0, v10 = t0.y + c0.y * s0;
        float u11 = t1.x + c1.x * s1, v11 = t1.y + c1.y * s1;
        const float2 l0 = __ldg(li2 + p0);
        const float2 l1 = __ldg(li2 + p1c);
        float la[8], lb[8];
        bilin8(reinterpret_cast<const float4*>(rgb_tex), u10, v10, la);
        bilin8(reinterpret_cast<const float4*>(rgb_tex), u11, v11, lb);
        col[0 * THREADS] = make_float2(l0.x, l1.x);
        col[1 * THREADS] = make_float2(l0.y, l1.y);
        col[2 * THREADS] = make_float2(c0.x, c1.x);
        col[3 * THREADS] = make_float2(c0.y, c1.y);
#pragma unroll
        for (int c = 0; c < 8; c++)
            col[(4 + c) * THREADS] = make_float2(la[c], lb[c]);
    }

    // ---- rgb MLP ----
    layerM<RW0_KC, 12 - RW0_KC>(cw.rw0T, swt.rw0, cw.rb0, col);
    layerM<RW1_KC, 32 - RW1_KC>(cw.rw1T, swt.rw1, cw.rb1, col);
    layerM<RW2_KC, 32 - RW2_KC>(cw.rw2T, swt.rw2, cw.rb2, col);

    // ---- rgb head (packed over both points) ----
    float o00, o01, o02, o10, o11, o12;
    {
        float a, b;
        unpack2(head2(cw.rw3d[0], col), a, b);
        o00 = a + cw.rb3[0]; o10 = b + cw.rb3[0];
        unpack2(head2(cw.rw3d[1], col), a, b);
        o01 = a + cw.rb3[1]; o11 = b + cw.rb3[1];
        unpack2(head2(cw.rw3d[2], col), a, b);
        o02 = a + cw.rb3[2]; o12 = b + cw.rb3[2];
    }
    out[3 * p0 + 0] = o00;
    out[3 * p0 + 1] = o01;
    out[3 * p0 + 2] = o02;
    if (p1 < n) {
        out[3 * p1 + 0] = o10;
        out[3 * p1 + 1] = o11;
        out[3 * p1 + 2] = o12;
    }
}

extern "C" void kernel_launch(void* const* d_in, const int* in_sizes, int n_in,
                              void* d_out, int out_size) {
    const float* cam        = (const float*)d_in[0];
    const float* light      = (const float*)d_in[1];
    const float* uv         = (const float*)d_in[2];
    const float* offset_tex = (const float*)d_in[3];
    const float* rgb_tex    = (const float*)d_in[4];

    prep_kernel<<<1, 256>>>((const float*)d_in[5],  (const float*)d_in[6],
                            (const float*)d_in[7],  (const float*)d_in[8],
                            (const float*)d_in[9],  (const float*)d_in[10],
                            (const float*)d_in[11], (const float*)d_in[12],
                            (const float*)d_in[13], (const float*)d_in[14],
                            (const float*)d_in[15], (const float*)d_in[16],
                            (const float*)d_in[17], (const float*)d_in[18],
                            (const float*)d_in[19], (const float*)d_in[20]);

    void* stage_ptr = nullptr;
    cudaGetSymbolAddress(&stage_ptr, g_stage);
    cudaMemcpyToSymbolAsync(cw, stage_ptr, sizeof(CW), 0,
                            cudaMemcpyDeviceToDevice, 0);

    const int n = in_sizes[0] / 2;  // camera_dir is (B, 2)
    const int blocks = (n + PTS_PER_BLOCK - 1) / PTS_PER_BLOCK;
    neumip_kernel<<<blocks, THREADS>>>(cam, light, uv, offset_tex, rgb_tex,
                                       (const float*)d_in[5],
                                       (const float*)d_in[7],
                                       (const float*)d_in[9],
                                       (const float*)d_in[13],
                                       (const float*)d_in[15],
                                       (const float*)d_in[17],
                                       (float*)d_out, n);
}